// round 12
// baseline (speedup 1.0000x reference)
#include <cuda_runtime.h>
#include <cstdint>

// ---------------------------------------------------------------------------
// SE3Net (all l=0): K(r) is a scalar function of pair distance, 0 for r>=4.5.
// K1 mlp : 16 blocks x 224 threads (NPTS=64, TM=4 rows). Weights arrive via
//          cp.async.bulk TMA ring (NO LDG in the layer loop). Thread =
//          (j-octant q, column-quad c4): 13 LDS.128 w + 13 LDS.128 h per
//          layer, 104 FFMA2, shfl q-combine, ONE barrier per layer.
// K2 conv: 128 blocks x 288 threads = one wave. Warp-per-atom, NN table,
//          direct stores, fused relu+mean+linear epilogue via counters.
// ---------------------------------------------------------------------------

#define NPTS    64
#define OCP     52
#define CIN     23
#define FSTR    24
#define NB      286
#define BATCH   4
#define HDIM    100
#define CPAD    104
#define NLAYERS 49
#define RMAX    4.5f
#define DELTA   (RMAX / (float)(NPTS - 1))
#define INV_DELTA ((float)(NPTS - 1) / RMAX)

#define TM 4
#define GRID_MLP (NPTS / TM)            // 16
#define MLP_THREADS 224                 // 7 warps
#define LAYER_FLOATS (HDIM * HDIM)      // 10000
#define LAYER_BYTES  (LAYER_FLOATS * 4) // 40000

#define ATOMS_PB 9
#define BLK_PER_BATCH 32                // 32*9 = 288 >= 286
#define CONV_THREADS 288                // 9 warps

typedef unsigned long long ull;

__device__ __align__(16) float g_table[NPTS * OCP];
__device__ float g_rows[BATCH * NB * 2];
__device__ int   g_ctr[BATCH];

__device__ __forceinline__ ull ffma2(ull a, ull b, ull c) {
    ull d;
    asm("fma.rn.f32x2 %0, %1, %2, %3;" : "=l"(d) : "l"(a), "l"(b), "l"(c));
    return d;
}
__device__ __forceinline__ ull add2(ull a, ull b) {
    ull d;
    asm("add.rn.f32x2 %0, %1, %2;" : "=l"(d) : "l"(a), "l"(b));
    return d;
}
__device__ __forceinline__ ull pack2(float lo, float hi) {
    ull d;
    asm("mov.b64 %0, {%1, %2};" : "=l"(d) : "f"(lo), "f"(hi));
    return d;
}
__device__ __forceinline__ float2 unpack2(ull v) {
    float lo, hi;
    asm("mov.b64 {%0, %1}, %2;" : "=f"(lo), "=f"(hi) : "l"(v));
    return make_float2(lo, hi);
}
__device__ __forceinline__ uint32_t s2u(const void* p) {
    return (uint32_t)__cvta_generic_to_shared(p);
}
__device__ __forceinline__ void mbar_init(uint32_t m, uint32_t cnt) {
    asm volatile("mbarrier.init.shared.b64 [%0], %1;" :: "r"(m), "r"(cnt)
                 : "memory");
}
__device__ __forceinline__ void mbar_expect_tx(uint32_t m, uint32_t bytes) {
    asm volatile("mbarrier.arrive.expect_tx.shared.b64 _, [%0], %1;"
                 :: "r"(m), "r"(bytes) : "memory");
}
__device__ __forceinline__ void bulk_g2s(uint32_t dst, const void* src,
                                         uint32_t bytes, uint32_t m) {
    asm volatile(
        "cp.async.bulk.shared::cta.global.mbarrier::complete_tx::bytes "
        "[%0], [%1], %2, [%3];"
        :: "r"(dst), "l"(src), "r"(bytes), "r"(m) : "memory");
}
__device__ __forceinline__ void mbar_wait(uint32_t m, uint32_t parity) {
    asm volatile(
        "{\n\t"
        ".reg .pred P;\n"
        "W%=:\n\t"
        "mbarrier.try_wait.parity.acquire.cta.shared::cta.b64 P, [%0], %1, 0x989680;\n\t"
        "@P bra D%=;\n\t"
        "bra W%=;\n"
        "D%=:\n\t"
        "}"
        :: "r"(m), "r"(parity) : "memory");
}
__device__ __forceinline__ float bump(float x) {
    float ax = fabsf(x);
    if (ax >= 1.0f) return 0.0f;
    float c = cosf(1.5707963267948966f * x);
    return c * c;
}

// ---------------------------------------------------------------------------
// Kernel 1: grid MLP. TMA-fed weights; (q, c4) threads; shfl combine.
// ---------------------------------------------------------------------------
__global__ void __launch_bounds__(MLP_THREADS, 1) mlp_table_kernel(
    const float* __restrict__ w_in,    // [3,100]
    const float* __restrict__ w_h,     // [49,100,100]
    const float* __restrict__ w_out)   // [100,46]
{
    extern __shared__ __align__(16) float ring[];   // 2 * 10000 floats
    __shared__ __align__(16) ull h2[2][CPAD][2];    // [buf][c][rowpair]
    __shared__ __align__(8) ull mbar[2];

    const int tid = threadIdx.x;
    const int wrp = tid >> 5;
    const int ln  = tid & 31;
    const int q   = ln >> 2;                  // j-octant 0..7
    const int c4  = (wrp << 2) | (ln & 3);    // column quad 0..27
    const int c4e = (c4 < 25) ? c4 : 24;      // clamp for in-bounds loads
    const int m0  = blockIdx.x * TM;

    if (tid == 0) { mbar_init(s2u(&mbar[0]), 1); mbar_init(s2u(&mbar[1]), 1); }
    __syncthreads();
    if (tid == 0) {
        mbar_expect_tx(s2u(&mbar[0]), LAYER_BYTES);
        bulk_g2s(s2u(ring), w_h, LAYER_BYTES, s2u(&mbar[0]));
        mbar_expect_tx(s2u(&mbar[1]), LAYER_BYTES);
        bulk_g2s(s2u(ring + LAYER_FLOATS), w_h + LAYER_FLOATS, LAYER_BYTES,
                 s2u(&mbar[1]));
    }

    // zero h pads j in [100,104) for BOTH buffers
    if (tid < 16) {
        int b = tid >> 3, idx = tid & 7;
        h2[b][HDIM + (idx >> 1)][idx & 1] = 0ULL;
    }

    // ---- input layer: basis -> h. q==0 lanes (ln<4) cover c4 0..27 ----
    if (ln < 4) {
        const float inv_sqrt3 = 0.57735026918962576f;
#pragma unroll
        for (int cc = 0; cc < 4; cc++) {
            int c = 4 * c4 + cc;
            if (c < HDIM) {
                float wi0 = w_in[c], wi1 = w_in[HDIM + c],
                      wi2 = w_in[2 * HDIM + c];
                float v[TM];
#pragma unroll
                for (int r = 0; r < TM; r++) {
                    float rr = (float)(m0 + r) * DELTA;
                    float b0 = bump(rr * (1.0f / 1.5f));
                    float b1 = bump((rr - 1.5f) * (1.0f / 1.5f));
                    float b2 = bump((rr - 3.0f) * (1.0f / 1.5f));
                    float a = (b0 * wi0 + b1 * wi1 + b2 * wi2) * inv_sqrt3;
                    v[r] = fmaxf(a, 0.0f);
                }
                ulonglong2 hv;
                hv.x = pack2(v[0], v[1]);
                hv.y = pack2(v[2], v[3]);
                *reinterpret_cast<ulonglong2*>(&h2[0][c][0]) = hv;
            }
        }
    }
    __syncthreads();

    int cur = 0;
#pragma unroll 1
    for (int l = 0; l < NLAYERS; l++) {
        mbar_wait(s2u(&mbar[l & 1]), (l >> 1) & 1);
        const float* __restrict__ ws = ring + (l & 1) * LAYER_FLOATS;

        ull acc[4][2];
#pragma unroll
        for (int cc = 0; cc < 4; cc++) { acc[cc][0] = 0ULL; acc[cc][1] = 0ULL; }

#pragma unroll
        for (int t = 0; t < 13; t++) {
            int j = 13 * q + t;
            int jeff = (j < HDIM) ? j : (HDIM - 1);
            // h for j (zero when j>=100 kills the garbage-weight product)
            ulonglong2 h01 = *reinterpret_cast<const ulonglong2*>(
                &h2[cur][j][0]);
            float4 w4 = *reinterpret_cast<const float4*>(
                ws + jeff * HDIM + 4 * c4e);
            ull p0 = pack2(w4.x, w4.x);
            ull p1 = pack2(w4.y, w4.y);
            ull p2 = pack2(w4.z, w4.z);
            ull p3 = pack2(w4.w, w4.w);
            acc[0][0] = ffma2(h01.x, p0, acc[0][0]);
            acc[0][1] = ffma2(h01.y, p0, acc[0][1]);
            acc[1][0] = ffma2(h01.x, p1, acc[1][0]);
            acc[1][1] = ffma2(h01.y, p1, acc[1][1]);
            acc[2][0] = ffma2(h01.x, p2, acc[2][0]);
            acc[2][1] = ffma2(h01.y, p2, acc[2][1]);
            acc[3][0] = ffma2(h01.x, p3, acc[3][0]);
            acc[3][1] = ffma2(h01.y, p3, acc[3][1]);
        }

        // combine 8 q-octants: q lives in lane bits 2..4
#pragma unroll
        for (int off = 4; off <= 16; off <<= 1) {
#pragma unroll
            for (int cc = 0; cc < 4; cc++) {
                acc[cc][0] = add2(acc[cc][0],
                                  __shfl_xor_sync(0xffffffffu, acc[cc][0], off));
                acc[cc][1] = add2(acc[cc][1],
                                  __shfl_xor_sync(0xffffffffu, acc[cc][1], off));
            }
        }

        if (ln < 4) {   // q==0 lanes hold the full sums
#pragma unroll
            for (int cc = 0; cc < 4; cc++) {
                int c = 4 * c4 + cc;
                if (c < HDIM) {
                    float2 v0 = unpack2(acc[cc][0]);
                    float2 v1 = unpack2(acc[cc][1]);
                    ulonglong2 hv;
                    hv.x = pack2(fmaxf(v0.x * 0.1f, 0.0f),
                                 fmaxf(v0.y * 0.1f, 0.0f));
                    hv.y = pack2(fmaxf(v1.x * 0.1f, 0.0f),
                                 fmaxf(v1.y * 0.1f, 0.0f));
                    *reinterpret_cast<ulonglong2*>(&h2[cur ^ 1][c][0]) = hv;
                }
            }
        }
        __syncthreads();    // h ready AND all reads of ring slot done

        if (tid == 0 && l + 2 < NLAYERS) {
            uint32_t mb = s2u(&mbar[l & 1]);
            mbar_expect_tx(mb, LAYER_BYTES);
            bulk_g2s(s2u(ring + (l & 1) * LAYER_FLOATS),
                     w_h + (size_t)(l + 2) * LAYER_FLOATS, LAYER_BYTES, mb);
        }
        cur ^= 1;
    }

    // ---- output layer: 46 outputs x 4 rows = 184 threads ----
    if (tid < 2 * CIN * TM) {
        int o = tid % (2 * CIN);
        int r = tid / (2 * CIN);
        const float* hp = reinterpret_cast<const float*>(&h2[cur][0][0])
                          + (r >> 1) * 2 + (r & 1);
        float acc = 0.0f;
#pragma unroll 4
        for (int j = 0; j < HDIM; j++)
            acc = fmaf(hp[j * 4], w_out[j * (2 * CIN) + o], acc);
        const float SCALE = 0.1f * 0.28209479177387814f * 0.5f;
        int co = o % CIN, oo = o / CIN;
        g_table[(m0 + r) * OCP + co * 2 + oo] = acc * SCALE;
    }
    for (int z = tid; z < TM * (OCP - 2 * CIN); z += MLP_THREADS) {
        int r = z / (OCP - 2 * CIN);
        int pos = 2 * CIN + z % (OCP - 2 * CIN);
        g_table[(m0 + r) * OCP + pos] = 0.0f;
    }
}

// ---------------------------------------------------------------------------
// Kernel 2: conv, one wave (128 blocks x 288 threads), fused epilogue.
// ---------------------------------------------------------------------------
__global__ void __launch_bounds__(CONV_THREADS) conv_kernel(
    const float* __restrict__ features,   // [B,N,23]
    const float* __restrict__ geometry,   // [B,N,3]
    const float* __restrict__ lin_w,      // [2]
    const float* __restrict__ lin_b,      // [1]
    float* __restrict__ out)              // [B]
{
    __shared__ __align__(16) float table_s[NPTS * OCP];    // 13.3 KB
    __shared__ __align__(16) float feat_s[NB * FSTR];      // 27.5 KB
    __shared__ __align__(16) float geo_s[NB * 4];          // 4.6 KB
    __shared__ float red0[CONV_THREADS];
    __shared__ float red1[CONV_THREADS];
    __shared__ int last_flag;

    const int tid = threadIdx.x;
    const int wrp = tid >> 5;
    const int ln  = tid & 31;
    const int b = blockIdx.y;
    const int grp = blockIdx.x;

    for (int k = tid; k < (NPTS * OCP) / 4; k += CONV_THREADS)
        reinterpret_cast<float4*>(table_s)[k] =
            reinterpret_cast<const float4*>(g_table)[k];
    const float* fb = features + (size_t)b * NB * CIN;
    for (int jr = wrp; jr < NB; jr += CONV_THREADS / 32) {
        if (ln < FSTR)
            feat_s[jr * FSTR + ln] = (ln < CIN) ? fb[jr * CIN + ln] : 0.0f;
    }
    const float* gb = geometry + (size_t)b * NB * 3;
    for (int k = tid; k < NB * 4; k += CONV_THREADS) {
        int j = k >> 2, d = k & 3;
        geo_s[k] = (d < 3) ? gb[j * 3 + d] : 0.0f;
    }
    __syncthreads();

    const int i = grp * ATOMS_PB + wrp;     // 9 warps -> 9 atoms
    if (i < NB) {
        float gx = geo_s[i * 4], gy = geo_s[i * 4 + 1], gz = geo_s[i * 4 + 2];
        ull acc = 0ULL;
        for (int j = ln; j < NB; j += 32) {
            float4 g4 = *reinterpret_cast<const float4*>(geo_s + j * 4);
            float dx = g4.x - gx, dy = g4.y - gy, dz = g4.z - gz;
            float r = sqrtf(fmaf(dx, dx, fmaf(dy, dy, fmaf(dz, dz, 1e-12f))));
            int u = __float2int_rn(r * INV_DELTA);
            if (u < NPTS) {
                const ulonglong2* __restrict__ T =
                    reinterpret_cast<const ulonglong2*>(table_s + u * OCP);
                const float4* __restrict__ f4 =
                    reinterpret_cast<const float4*>(feat_s + j * FSTR);
                ull d0 = 0ULL, d1 = 0ULL;
#pragma unroll
                for (int k = 0; k < 6; k++) {
                    float4 f = f4[k];
                    ulonglong2 t0 = T[2 * k];
                    ulonglong2 t1 = T[2 * k + 1];
                    d0 = ffma2(t0.x, pack2(f.x, f.x), d0);
                    d1 = ffma2(t0.y, pack2(f.y, f.y), d1);
                    d0 = ffma2(t1.x, pack2(f.z, f.z), d0);
                    d1 = ffma2(t1.y, pack2(f.w, f.w), d1);
                }
                acc = add2(acc, add2(d0, d1));
            }
        }
        float2 av = unpack2(acc);
        float a0 = av.x, a1 = av.y;
#pragma unroll
        for (int off = 16; off > 0; off >>= 1) {
            a0 += __shfl_xor_sync(0xffffffffu, a0, off);
            a1 += __shfl_xor_sync(0xffffffffu, a1, off);
        }
        if (ln == 0) {                      // single writer: direct store
            g_rows[(b * NB + i) * 2 + 0] = fmaxf(a0, 0.0f);
            g_rows[(b * NB + i) * 2 + 1] = fmaxf(a1, 0.0f);
        }
    }

    // ---- fused epilogue: last block of this batch does mean + linear ----
    __threadfence();
    __syncthreads();
    if (tid == 0)
        last_flag = (atomicAdd(&g_ctr[b], 1) == BLK_PER_BATCH - 1) ? 1 : 0;
    __syncthreads();
    if (last_flag) {
        __threadfence();
        float s0 = 0.f, s1 = 0.f;
        for (int k = tid; k < NB; k += CONV_THREADS) {
            s0 += g_rows[(b * NB + k) * 2 + 0];
            s1 += g_rows[(b * NB + k) * 2 + 1];
        }
        red0[tid] = s0; red1[tid] = s1;
        __syncthreads();
        if (tid < CONV_THREADS - 256) {     // fold 288 -> 256
            red0[tid] += red0[tid + 256];
            red1[tid] += red1[tid + 256];
        }
        __syncthreads();
#pragma unroll
        for (int s = 128; s > 0; s >>= 1) {
            if (tid < s) { red0[tid] += red0[tid + s]; red1[tid] += red1[tid + s]; }
            __syncthreads();
        }
        if (tid == 0) {
            out[b] = (red0[0] * lin_w[0] + red1[0] * lin_w[1])
                     * (1.0f / (float)NB) + lin_b[0];
            g_ctr[b] = 0;                   // reset for next graph replay
        }
    }
}

// ---------------------------------------------------------------------------
extern "C" void kernel_launch(void* const* d_in, const int* in_sizes, int n_in,
                              void* d_out, int out_size) {
    int o = 0;
    if (n_in >= 4 && in_sizes[2] == 1) o = 1;   // num_atoms scalar present

    const float* features = (const float*)d_in[0];
    const float* geometry = (const float*)d_in[1];
    const float* w_in     = (const float*)d_in[2 + o];
    const float* w_h      = (const float*)d_in[3 + o];
    const float* w_out    = (const float*)d_in[4 + o];
    const float* lin_w    = (const float*)d_in[5 + o];
    const float* lin_b    = (const float*)d_in[6 + o];

    const int mlp_smem = 2 * LAYER_BYTES;       // 80 KB ring
    cudaFuncSetAttribute(mlp_table_kernel,
                         cudaFuncAttributeMaxDynamicSharedMemorySize, mlp_smem);

    mlp_table_kernel<<<GRID_MLP, MLP_THREADS, mlp_smem>>>(w_in, w_h, w_out);
    conv_kernel<<<dim3(BLK_PER_BATCH, BATCH), CONV_THREADS>>>(
        features, geometry, lin_w, lin_b, (float*)d_out);
}

// round 13
// speedup vs baseline: 1.1654x; 1.1654x over previous
#include <cuda_runtime.h>
#include <cstdint>

// ---------------------------------------------------------------------------
// SE3Net (all l=0): K(r) is a scalar function of distance, zero for r>=4.5.
// R6 (best measured: 64.0us) with ONE change: NPTS 128 -> 32 (validated
// rel_err 0.0 in R9/R10). Conv table staging drops 26.6KB -> 6.7KB per block.
// K1: grid MLP, 8 blocks x 400 threads. Thread = (column c, j-quarter q).
//     Weights in REGISTERS (coalesced LDG.32, one layer lookahead);
//     h broadcast SMEM vector; per-layer combine over 4 q-partials.
// K2: conv, nearest-neighbor table, stride-tuned SMEM, 288 blocks,
//     atomicAdd(2 addends, exact) + counter epilogue (mean+linear fused).
// ---------------------------------------------------------------------------

#define NPTS    32
#define OCP     52          // table row stride (floats)
#define CIN     23
#define FSTR    28          // feature row stride (floats)
#define NB      286
#define BATCH   4
#define HDIM    100
#define NLAYERS 49
#define RMAX    4.5f
#define DELTA   (RMAX / (float)(NPTS - 1))
#define INV_DELTA ((float)(NPTS - 1) / RMAX)

#define TM 4
#define GRID_MLP (NPTS / TM)        // 8
#define QD 4                        // j-quarter split
#define JPQ (HDIM / QD)             // 25
#define MLP_THREADS (QD * HDIM)     // 400

#define ATOMS_PB 8
#define CONV_THREADS 256
#define NBXC ((NB + ATOMS_PB - 1) / ATOMS_PB)   // 36
#define JSPLIT 2
#define BLOCKS_PER_BATCH (NBXC * JSPLIT)        // 72

typedef unsigned long long ull;

__device__ __align__(16) float g_table[NPTS * OCP];
__device__ float g_rows[BATCH * NB * 2];
__device__ int   g_ctr[BATCH];

__device__ __forceinline__ ull ffma2(ull a, ull b, ull c) {
    ull d;
    asm("fma.rn.f32x2 %0, %1, %2, %3;" : "=l"(d) : "l"(a), "l"(b), "l"(c));
    return d;
}
__device__ __forceinline__ ull add2(ull a, ull b) {
    ull d;
    asm("add.rn.f32x2 %0, %1, %2;" : "=l"(d) : "l"(a), "l"(b));
    return d;
}
__device__ __forceinline__ ull pack2(float lo, float hi) {
    ull d;
    asm("mov.b64 %0, {%1, %2};" : "=l"(d) : "f"(lo), "f"(hi));
    return d;
}
__device__ __forceinline__ float2 unpack2(ull v) {
    float lo, hi;
    asm("mov.b64 {%0, %1}, %2;" : "=f"(lo), "=f"(hi) : "l"(v));
    return make_float2(lo, hi);
}
__device__ __forceinline__ float bump(float x) {
    float ax = fabsf(x);
    if (ax >= 1.0f) return 0.0f;
    float c = cosf(1.5707963267948966f * x);
    return c * c;
}

// ---------------------------------------------------------------------------
// Kernel 1: grid MLP, register-resident weights. (R6 verbatim)
// ---------------------------------------------------------------------------
__global__ void __launch_bounds__(MLP_THREADS) mlp_table_kernel(
    const float* __restrict__ w_in,    // [3,100]
    const float* __restrict__ w_h,     // [49,100,100]
    const float* __restrict__ w_out)   // [100,46]
{
    __shared__ __align__(16) ull h2[2][HDIM][2];    // [buf][j][rowpair]
    __shared__ __align__(16) ull part[QD][HDIM][2];

    const int tid = threadIdx.x;
    const int m0  = blockIdx.x * TM;
    const int q   = tid / HDIM;        // 0..3
    const int c   = tid % HDIM;        // 0..99
    const int j0  = q * JPQ;

    float wcur[JPQ], wnxt[JPQ];
    // prologue: layer-0 hidden weights, coalesced LDG.32
    {
        const float* base = w_h + c;
#pragma unroll
        for (int jj = 0; jj < JPQ; jj++)
            wcur[jj] = base[(j0 + jj) * HDIM];
    }

    // ---- layer 0: basis -> h ----
    if (tid < HDIM) {
        const float inv_sqrt3 = 0.57735026918962576f;
        float wi0 = w_in[tid], wi1 = w_in[HDIM + tid], wi2 = w_in[2 * HDIM + tid];
        float v[TM];
#pragma unroll
        for (int r = 0; r < TM; r++) {
            float rr = (float)(m0 + r) * DELTA;
            float b0 = bump(rr * (1.0f / 1.5f));
            float b1 = bump((rr - 1.5f) * (1.0f / 1.5f));
            float b2 = bump((rr - 3.0f) * (1.0f / 1.5f));
            float a = (b0 * wi0 + b1 * wi1 + b2 * wi2) * inv_sqrt3;
            v[r] = fmaxf(a, 0.0f);
        }
        h2[0][tid][0] = pack2(v[0], v[1]);
        h2[0][tid][1] = pack2(v[2], v[3]);
    }
    __syncthreads();

    int cur = 0;
#pragma unroll 1
    for (int l = 0; l < NLAYERS; l++) {
        // prefetch next layer's weights into registers (hidden behind compute)
        if (l + 1 < NLAYERS) {
            const float* base = w_h + (size_t)(l + 1) * (HDIM * HDIM) + c;
#pragma unroll
            for (int jj = 0; jj < JPQ; jj++)
                wnxt[jj] = base[(j0 + jj) * HDIM];
        }

        // 25 MACs into 2x2 partial accumulators (split chains)
        ull a0 = 0, a1 = 0, b0 = 0, b1 = 0;
#pragma unroll
        for (int jj = 0; jj < JPQ; jj += 2) {
            {
                ulonglong2 hv = *reinterpret_cast<const ulonglong2*>(
                    &h2[cur][j0 + jj][0]);
                ull pw = pack2(wcur[jj], wcur[jj]);
                a0 = ffma2(hv.x, pw, a0);
                a1 = ffma2(hv.y, pw, a1);
            }
            if (jj + 1 < JPQ) {
                ulonglong2 hv = *reinterpret_cast<const ulonglong2*>(
                    &h2[cur][j0 + jj + 1][0]);
                ull pw = pack2(wcur[jj + 1], wcur[jj + 1]);
                b0 = ffma2(hv.x, pw, b0);
                b1 = ffma2(hv.y, pw, b1);
            }
        }
        part[q][c][0] = add2(a0, b0);
        part[q][c][1] = add2(a1, b1);
        __syncthreads();

        if (tid < HDIM) {
            ull s0 = add2(add2(part[0][tid][0], part[1][tid][0]),
                          add2(part[2][tid][0], part[3][tid][0]));
            ull s1 = add2(add2(part[0][tid][1], part[1][tid][1]),
                          add2(part[2][tid][1], part[3][tid][1]));
            float2 v0 = unpack2(s0), v1 = unpack2(s1);
            h2[cur ^ 1][tid][0] = pack2(fmaxf(v0.x * 0.1f, 0.0f),
                                        fmaxf(v0.y * 0.1f, 0.0f));
            h2[cur ^ 1][tid][1] = pack2(fmaxf(v1.x * 0.1f, 0.0f),
                                        fmaxf(v1.y * 0.1f, 0.0f));
        }
        __syncthreads();

        if (l + 1 < NLAYERS) {
#pragma unroll
            for (int jj = 0; jj < JPQ; jj++) wcur[jj] = wnxt[jj];
        }
        cur ^= 1;
    }

    // ---- output layer: 46 cols x 4 rows = 184 threads; zero row pads ----
    if (tid < 2 * CIN * TM) {
        int o = tid % (2 * CIN);
        int r = tid / (2 * CIN);
        const float* hp = reinterpret_cast<const float*>(&h2[cur][0][0])
                          + (r >> 1) * 2 + (r & 1);
        float acc = 0.0f;
#pragma unroll 4
        for (int j = 0; j < HDIM; j++)
            acc = fmaf(hp[j * 4], w_out[j * (2 * CIN) + o], acc);
        const float SCALE = 0.1f * 0.28209479177387814f * 0.5f;
        int co = o % CIN, oo = o / CIN;
        g_table[(m0 + r) * OCP + co * 2 + oo] = acc * SCALE;
    }
    for (int z = tid; z < TM * (OCP - 2 * CIN); z += MLP_THREADS) {
        int r = z / (OCP - 2 * CIN);
        int pos = 2 * CIN + z % (OCP - 2 * CIN);
        g_table[(m0 + r) * OCP + pos] = 0.0f;
    }
}

// ---------------------------------------------------------------------------
// Kernel 2: pairwise conv (nearest-neighbor table), fused epilogue.
// (R6 verbatim; table now 6.7 KB)
// ---------------------------------------------------------------------------
__global__ void __launch_bounds__(CONV_THREADS) conv_kernel(
    const float* __restrict__ features,   // [B,N,23]
    const float* __restrict__ geometry,   // [B,N,3]
    const float* __restrict__ lin_w,      // [2]
    const float* __restrict__ lin_b,      // [1]
    float* __restrict__ out)              // [B]
{
    extern __shared__ __align__(16) float cs[];
    float* table_s = cs;                            // NPTS*OCP  (1664 f)
    float* feat_s  = cs + NPTS * OCP;               // NB*FSTR   (8008 f)
    float* geo_s   = feat_s + NB * FSTR;            // NB*4      (1144 f)
    __shared__ float red0[CONV_THREADS];
    __shared__ float red1[CONV_THREADS];
    __shared__ int last_flag;

    const int tid = threadIdx.x;
    const int b = blockIdx.z;
    const int js = blockIdx.y;                      // j-split 0..1

    for (int k = tid; k < (NPTS * OCP) / 4; k += CONV_THREADS)
        reinterpret_cast<float4*>(table_s)[k] =
            reinterpret_cast<const float4*>(g_table)[k];
    const float* fb = features + (size_t)b * NB * CIN;
    const float* gb = geometry + (size_t)b * NB * 3;
    for (int k = tid; k < NB * FSTR; k += CONV_THREADS) {
        int j = k / FSTR, cc = k % FSTR;
        feat_s[k] = (cc < CIN) ? fb[j * CIN + cc] : 0.0f;
    }
    for (int k = tid; k < NB * 4; k += CONV_THREADS) {
        int j = k >> 2, d = k & 3;
        geo_s[k] = (d < 3) ? gb[j * 3 + d] : 0.0f;
    }
    __syncthreads();

    const int wrp = tid >> 5;
    const int ln  = tid & 31;
    const int i = blockIdx.x * ATOMS_PB + wrp;
    const bool valid = (i < NB);
    float gx = 0.f, gy = 0.f, gz = 0.f;
    if (valid) { gx = geo_s[i * 4]; gy = geo_s[i * 4 + 1]; gz = geo_s[i * 4 + 2]; }

    const int jbeg = js * (NB / JSPLIT);
    const int jend = jbeg + (NB / JSPLIT);

    ull acc = 0ULL;
    for (int j = jbeg + ln; j < jend; j += 32) {
        float4 g4 = *reinterpret_cast<const float4*>(geo_s + j * 4);
        float dx = g4.x - gx, dy = g4.y - gy, dz = g4.z - gz;
        float r = sqrtf(fmaf(dx, dx, fmaf(dy, dy, fmaf(dz, dz, 1e-12f))));
        int u = __float2int_rn(r * INV_DELTA);
        if (valid && u < NPTS) {
            const ulonglong2* __restrict__ T =
                reinterpret_cast<const ulonglong2*>(table_s + u * OCP);
            const float4* __restrict__ f4 =
                reinterpret_cast<const float4*>(feat_s + j * FSTR);
            ull d0 = 0ULL, d1 = 0ULL;
#pragma unroll
            for (int k = 0; k < 6; k++) {
                float4 f = f4[k];
                ulonglong2 t0 = T[2 * k];
                ulonglong2 t1 = T[2 * k + 1];
                d0 = ffma2(t0.x, pack2(f.x, f.x), d0);
                d1 = ffma2(t0.y, pack2(f.y, f.y), d1);
                d0 = ffma2(t1.x, pack2(f.z, f.z), d0);
                d1 = ffma2(t1.y, pack2(f.w, f.w), d1);
            }
            acc = add2(acc, add2(d0, d1));
        }
    }

    float2 av = unpack2(acc);
    float acc0 = av.x, acc1 = av.y;
#pragma unroll
    for (int off = 16; off > 0; off >>= 1) {
        acc0 += __shfl_xor_sync(0xffffffffu, acc0, off);
        acc1 += __shfl_xor_sync(0xffffffffu, acc1, off);
    }
    if (ln == 0 && valid) {
        // exactly 2 addends per row (JSPLIT=2): commutative -> deterministic
        atomicAdd(&g_rows[(b * NB + i) * 2 + 0], acc0);
        atomicAdd(&g_rows[(b * NB + i) * 2 + 1], acc1);
    }

    // ---- fused epilogue: last block of this batch does relu+mean+linear ----
    __threadfence();
    __syncthreads();
    if (tid == 0)
        last_flag = (atomicAdd(&g_ctr[b], 1) == BLOCKS_PER_BATCH - 1) ? 1 : 0;
    __syncthreads();
    if (last_flag) {
        __threadfence();
        float s0 = 0.f, s1 = 0.f;
        for (int k = tid; k < NB; k += CONV_THREADS) {
            s0 += fmaxf(g_rows[(b * NB + k) * 2 + 0], 0.0f);
            s1 += fmaxf(g_rows[(b * NB + k) * 2 + 1], 0.0f);
            g_rows[(b * NB + k) * 2 + 0] = 0.0f;    // reset for next replay
            g_rows[(b * NB + k) * 2 + 1] = 0.0f;
        }
        red0[tid] = s0; red1[tid] = s1;
        __syncthreads();
#pragma unroll
        for (int s = CONV_THREADS / 2; s > 0; s >>= 1) {
            if (tid < s) { red0[tid] += red0[tid + s]; red1[tid] += red1[tid + s]; }
            __syncthreads();
        }
        if (tid == 0) {
            out[b] = (red0[0] * lin_w[0] + red1[0] * lin_w[1])
                     * (1.0f / (float)NB) + lin_b[0];
            g_ctr[b] = 0;                           // reset for next replay
        }
    }
}

// ---------------------------------------------------------------------------
extern "C" void kernel_launch(void* const* d_in, const int* in_sizes, int n_in,
                              void* d_out, int out_size) {
    int o = 0;
    if (n_in >= 4 && in_sizes[2] == 1) o = 1;   // num_atoms scalar present

    const float* features = (const float*)d_in[0];
    const float* geometry = (const float*)d_in[1];
    const float* w_in     = (const float*)d_in[2 + o];
    const float* w_h      = (const float*)d_in[3 + o];
    const float* w_out    = (const float*)d_in[4 + o];
    const float* lin_w    = (const float*)d_in[5 + o];
    const float* lin_b    = (const float*)d_in[6 + o];

    const int conv_smem = (NPTS * OCP + NB * FSTR + NB * 4) * (int)sizeof(float);
    cudaFuncSetAttribute(conv_kernel,
                         cudaFuncAttributeMaxDynamicSharedMemorySize, conv_smem);

    mlp_table_kernel<<<GRID_MLP, MLP_THREADS>>>(w_in, w_h, w_out);
    conv_kernel<<<dim3(NBXC, JSPLIT, BATCH), CONV_THREADS, conv_smem>>>(
        features, geometry, lin_w, lin_b, (float*)d_out);
}